// round 2
// baseline (speedup 1.0000x reference)
#include <cuda_runtime.h>
#include <math.h>

#define CLASSES 21
#define MAXT 512
#define MAXBLOCKS 2048

// Per-block partial sums (deterministic two-stage reduction; no atomics).
__device__ float g_partial_cls[MAXBLOCKS];
__device__ float g_partial_reg[MAXBLOCKS];
__device__ float g_partial_pos[MAXBLOCKS];

__device__ __forceinline__ float warp_red(float v) {
    #pragma unroll
    for (int o = 16; o > 0; o >>= 1) v += __shfl_down_sync(0xffffffffu, v, o);
    return v;
}

__global__ void __launch_bounds__(256)
retina_main(const float* __restrict__ cls,
            const float4* __restrict__ box,
            const float4* __restrict__ anc,
            const float4* __restrict__ tb,
            const int* __restrict__ tl,
            int A, int T)
{
    __shared__ float4 s_tb[MAXT];
    __shared__ float  s_ta[MAXT];
    __shared__ int    s_tl[MAXT];

    for (int t = threadIdx.x; t < T; t += blockDim.x) {
        float4 b = tb[t];
        s_tb[t] = b;
        s_ta[t] = (b.z - b.x) * (b.w - b.y);
        s_tl[t] = tl[t];
    }
    __syncthreads();

    int a = blockIdx.x * blockDim.x + threadIdx.x;
    float cls_sum = 0.f, reg_sum = 0.f, posf = 0.f;

    if (a < A) {
        float4 an = anc[a];
        float areaA = (an.z - an.x) * (an.w - an.y);

        // argmax over targets via cross-multiplication (no divisions in loop).
        // Strict '>' keeps the FIRST index achieving the max (jnp.argmax semantics).
        float bi = 0.f;   // best intersection
        float bu = 1.f;   // best union (1 so initial iou==0)
        int   bidx = 0;

        #pragma unroll 4
        for (int t = 0; t < T; ++t) {
            float4 tbx = s_tb[t];
            float w = fminf(an.z, tbx.z) - fmaxf(an.x, tbx.x);
            float h = fminf(an.w, tbx.w) - fmaxf(an.y, tbx.y);
            w = fmaxf(w, 0.f);
            h = fmaxf(h, 0.f);
            float inter = w * h;
            float uni   = areaA + s_ta[t] - inter;
            bool upd = inter * bu > bi * uni;
            bi   = upd ? inter : bi;
            bu   = upd ? uni   : bu;
            bidx = upd ? t     : bidx;
        }

        // Reproduce reference rounding for the threshold test (IEEE div).
        float iou = bi / fmaxf(bu, 1e-8f);
        bool pos = (iou >= 0.5f);
        posf = pos ? 1.f : 0.f;
        int lbl = pos ? s_tl[bidx] : 0;   // background one-hot hits class 0

        // ---- focal loss over 21 classes ----
        // t==1 at class lbl. z = t?x:-x ; ce = -logsigmoid(z) ; 1-pt = sigmoid(-z)
        const float* cp = cls + (size_t)a * CLASSES;
        #pragma unroll
        for (int c = 0; c < CLASSES; ++c) {
            float x = cp[c];
            bool tgt = (c == lbl);
            float z = tgt ? x : -x;
            float e   = expf(-fabsf(z));
            float l1p = log1pf(e);
            float ce  = (z < 0.f) ? (l1p - z) : l1p;
            float r   = 1.f / (1.f + e);
            float q   = (z >= 0.f) ? (e * r) : r;   // = sigmoid(-z) = 1 - pt
            float alpha = tgt ? 0.25f : 0.75f;
            cls_sum += alpha * q * q * ce;
        }

        // ---- regression loss (positives only; negatives are masked to 0) ----
        if (pos) {
            float4 bp = box[a];
            float4 tg = s_tb[bidx];
            float awx = an.z - an.x, awy = an.w - an.y;
            float acx = (an.x + an.z) * 0.5f, acy = (an.y + an.w) * 0.5f;

            float pcx = (bp.x + bp.z) * 0.5f, pcy = (bp.y + bp.w) * 0.5f;
            float pwx = bp.z - bp.x,          pwy = bp.w - bp.y;
            float ep0 = (pcx - acx) / awx;
            float ep1 = (pcy - acy) / awy;
            float ep2 = logf(pwx / awx);
            float ep3 = logf(pwy / awy);

            float tcx = (tg.x + tg.z) * 0.5f, tcy = (tg.y + tg.w) * 0.5f;
            float twx = tg.z - tg.x,          twy = tg.w - tg.y;
            float et0 = (tcx - acx) / awx;
            float et1 = (tcy - acy) / awy;
            float et2 = logf(twx / awx);
            float et3 = logf(twy / awy);

            float d;
            d = fabsf(ep0 - et0); reg_sum += (d < 1.f) ? 0.5f * d * d : d - 0.5f;
            d = fabsf(ep1 - et1); reg_sum += (d < 1.f) ? 0.5f * d * d : d - 0.5f;
            d = fabsf(ep2 - et2); reg_sum += (d < 1.f) ? 0.5f * d * d : d - 0.5f;
            d = fabsf(ep3 - et3); reg_sum += (d < 1.f) ? 0.5f * d * d : d - 0.5f;
        }
    }

    // ---- block reduction (fixed order, deterministic) ----
    __shared__ float red_c[8], red_r[8], red_p[8];
    float vc = warp_red(cls_sum);
    float vr = warp_red(reg_sum);
    float vp = warp_red(posf);
    int wid = threadIdx.x >> 5, lid = threadIdx.x & 31;
    if (lid == 0) { red_c[wid] = vc; red_r[wid] = vr; red_p[wid] = vp; }
    __syncthreads();
    if (wid == 0) {
        float c2 = (lid < 8) ? red_c[lid] : 0.f;
        float r2 = (lid < 8) ? red_r[lid] : 0.f;
        float p2 = (lid < 8) ? red_p[lid] : 0.f;
        c2 = warp_red(c2);
        r2 = warp_red(r2);
        p2 = warp_red(p2);
        if (lid == 0) {
            g_partial_cls[blockIdx.x] = c2;
            g_partial_reg[blockIdx.x] = r2;
            g_partial_pos[blockIdx.x] = p2;
        }
    }
}

__global__ void __launch_bounds__(256)
retina_final(float* __restrict__ out, int nblocks)
{
    double c = 0.0, r = 0.0, p = 0.0;
    for (int i = threadIdx.x; i < nblocks; i += blockDim.x) {
        c += (double)g_partial_cls[i];
        r += (double)g_partial_reg[i];
        p += (double)g_partial_pos[i];
    }
    // warp + block reduce in double (fixed order)
    #pragma unroll
    for (int o = 16; o > 0; o >>= 1) {
        c += __shfl_down_sync(0xffffffffu, c, o);
        r += __shfl_down_sync(0xffffffffu, r, o);
        p += __shfl_down_sync(0xffffffffu, p, o);
    }
    __shared__ double sc[8], sr[8], sp[8];
    int wid = threadIdx.x >> 5, lid = threadIdx.x & 31;
    if (lid == 0) { sc[wid] = c; sr[wid] = r; sp[wid] = p; }
    __syncthreads();
    if (threadIdx.x == 0) {
        double tc = 0.0, tr = 0.0, tp = 0.0;
        #pragma unroll
        for (int i = 0; i < 8; ++i) { tc += sc[i]; tr += sr[i]; tp += sp[i]; }
        float pos_cnt = (float)tp;
        float norm = fmaxf(pos_cnt, 1.f);
        float cls_loss = (float)tc / norm;
        float reg_loss = (pos_cnt > 0.f) ? ((float)tr / (norm * 4.f)) : 0.f;
        float wc = cls_loss * 1.0f;   // CLS_W
        float wr = reg_loss * 1.0f;   // REG_W
        out[0] = wc + wr;
        out[1] = wc;
        out[2] = wr;
    }
}

extern "C" void kernel_launch(void* const* d_in, const int* in_sizes, int n_in,
                              void* d_out, int out_size)
{
    const float*  cls = (const float*)d_in[0];
    const float4* box = (const float4*)d_in[1];
    const float4* anc = (const float4*)d_in[2];
    const float4* tb  = (const float4*)d_in[3];
    const int*    tl  = (const int*)d_in[4];
    float* out = (float*)d_out;

    int A = in_sizes[2] / 4;   // flattened anchor count (B*A)
    int T = in_sizes[4];       // flattened target count (B*T)
    if (T > MAXT) T = MAXT;    // capacity guard (T=200 here)

    int nblocks = (A + 255) / 256;
    if (nblocks > MAXBLOCKS) nblocks = MAXBLOCKS;  // A=196608 -> 768

    retina_main<<<nblocks, 256>>>(cls, box, anc, tb, tl, A, T);
    retina_final<<<1, 256>>>(out, nblocks);
}

// round 3
// speedup vs baseline: 1.0818x; 1.0818x over previous
#include <cuda_runtime.h>
#include <math.h>

#define CLASSES 21
#define MAXT 512
#define TPB 256
#define APT 2          // anchors per thread
#define MAXBLOCKS 4096

__device__ float g_pc[MAXBLOCKS];
__device__ float g_pr[MAXBLOCKS];
__device__ float g_pp[MAXBLOCKS];
__device__ int   g_count;   // zero-init; self-resets each launch

__device__ __forceinline__ float warp_red_f(float v) {
    #pragma unroll
    for (int o = 16; o > 0; o >>= 1) v += __shfl_down_sync(0xffffffffu, v, o);
    return v;
}
__device__ __forceinline__ double warp_red_d(double v) {
    #pragma unroll
    for (int o = 16; o > 0; o >>= 1) v += __shfl_down_sync(0xffffffffu, v, o);
    return v;
}

__global__ void __launch_bounds__(TPB)
retina_fused(const float* __restrict__ cls,
             const float4* __restrict__ box,
             const float4* __restrict__ anc,
             const float4* __restrict__ tb,
             const int* __restrict__ tl,
             float* __restrict__ out,
             int A, int T)
{
    __shared__ float4 s_tb[MAXT];
    __shared__ float  s_ta[MAXT];
    __shared__ int    s_tl[MAXT];

    for (int t = threadIdx.x; t < T; t += TPB) {
        float4 b = tb[t];
        s_tb[t] = b;
        s_ta[t] = (b.z - b.x) * (b.w - b.y);
        s_tl[t] = tl[t];
    }
    __syncthreads();

    const int g  = blockIdx.x * TPB + threadIdx.x;
    float cls_sum = 0.f, reg_sum = 0.f, posf = 0.f;

    float4 an[APT];
    float  areaA[APT];
    float  br[APT];
    int    bidx[APT];
    bool   valid[APT];

    #pragma unroll
    for (int j = 0; j < APT; ++j) {
        int a = g * APT + j;
        valid[j] = (a < A);
        if (valid[j]) {
            float4 v = anc[a];
            an[j] = v;
            areaA[j] = (v.z - v.x) * (v.w - v.y);
        } else {
            an[j] = make_float4(0.f, 0.f, 0.f, 0.f);
            areaA[j] = 0.f;
        }
        br[j] = 0.f;
        bidx[j] = 0;
    }

    // ---- argmax IoU over targets (approx ratio via MUFU.RCP; exact check after) ----
    #pragma unroll 2
    for (int t = 0; t < T; ++t) {
        float4 tx = s_tb[t];
        float  ta = s_ta[t];
        #pragma unroll
        for (int j = 0; j < APT; ++j) {
            float w = fminf(an[j].z, tx.z) - fmaxf(an[j].x, tx.x);
            float h = fminf(an[j].w, tx.w) - fmaxf(an[j].y, tx.y);
            w = fmaxf(w, 0.f);                 // clamping w alone is sufficient:
            float inter = w * h;               // inter<=0 can never win r>br (br>=0)
            float uni   = (areaA[j] + ta) - inter;
            float r     = __fdividef(inter, uni);   // FMUL + MUFU.RCP (idle pipe)
            bool upd = r > br[j];
            br[j]   = fmaxf(br[j], r);
            bidx[j] = upd ? t : bidx[j];
        }
    }

    // ---- per-anchor epilogue ----
    #pragma unroll
    for (int j = 0; j < APT; ++j) {
        if (!valid[j]) continue;
        int a = g * APT + j;

        // exact IoU for the winning target (IEEE division, reference rounding)
        float4 tg = s_tb[bidx[j]];
        float  ta = s_ta[bidx[j]];
        float w = fmaxf(fminf(an[j].z, tg.z) - fmaxf(an[j].x, tg.x), 0.f);
        float h = fmaxf(fminf(an[j].w, tg.w) - fmaxf(an[j].y, tg.y), 0.f);
        float inter = w * h;
        float uni   = areaA[j] + ta - inter;
        float iou   = __fdiv_rn(inter, fmaxf(uni, 1e-8f));
        bool pos = (iou >= 0.5f);
        posf += pos ? 1.f : 0.f;
        int lbl = pos ? s_tl[bidx[j]] : 0;   // negatives: background one-hot at class 0

        // ---- focal loss over 21 classes ----
        const float* cp = cls + (size_t)a * CLASSES;
        #pragma unroll
        for (int c = 0; c < CLASSES; ++c) {
            float x = cp[c];
            bool tgt = (c == lbl);
            float z = tgt ? x : -x;
            float e   = __expf(-fabsf(z));
            float l1p = __logf(1.f + e);
            float ce  = (z < 0.f) ? (l1p - z) : l1p;
            float rcp = __fdividef(1.f, 1.f + e);
            float q   = (z >= 0.f) ? (e * rcp) : rcp;   // sigmoid(-z) = 1 - pt
            float alpha = tgt ? 0.25f : 0.75f;
            cls_sum += alpha * q * q * ce;
        }

        // ---- regression (positives only) ----
        if (pos) {
            float4 bp = box[a];
            float awx = an[j].z - an[j].x, awy = an[j].w - an[j].y;
            float acx = (an[j].x + an[j].z) * 0.5f, acy = (an[j].y + an[j].w) * 0.5f;

            float ep0 = __fdiv_rn((bp.x + bp.z) * 0.5f - acx, awx);
            float ep1 = __fdiv_rn((bp.y + bp.w) * 0.5f - acy, awy);
            float ep2 = logf(__fdiv_rn(bp.z - bp.x, awx));
            float ep3 = logf(__fdiv_rn(bp.w - bp.y, awy));

            float et0 = __fdiv_rn((tg.x + tg.z) * 0.5f - acx, awx);
            float et1 = __fdiv_rn((tg.y + tg.w) * 0.5f - acy, awy);
            float et2 = logf(__fdiv_rn(tg.z - tg.x, awx));
            float et3 = logf(__fdiv_rn(tg.w - tg.y, awy));

            float d;
            d = fabsf(ep0 - et0); reg_sum += (d < 1.f) ? 0.5f * d * d : d - 0.5f;
            d = fabsf(ep1 - et1); reg_sum += (d < 1.f) ? 0.5f * d * d : d - 0.5f;
            d = fabsf(ep2 - et2); reg_sum += (d < 1.f) ? 0.5f * d * d : d - 0.5f;
            d = fabsf(ep3 - et3); reg_sum += (d < 1.f) ? 0.5f * d * d : d - 0.5f;
        }
    }

    // ---- deterministic block reduction ----
    __shared__ float red_c[8], red_r[8], red_p[8];
    float vc = warp_red_f(cls_sum);
    float vr = warp_red_f(reg_sum);
    float vp = warp_red_f(posf);
    int wid = threadIdx.x >> 5, lid = threadIdx.x & 31;
    if (lid == 0) { red_c[wid] = vc; red_r[wid] = vr; red_p[wid] = vp; }
    __syncthreads();
    if (wid == 0) {
        float c2 = (lid < 8) ? red_c[lid] : 0.f;
        float r2 = (lid < 8) ? red_r[lid] : 0.f;
        float p2 = (lid < 8) ? red_p[lid] : 0.f;
        c2 = warp_red_f(c2);
        r2 = warp_red_f(r2);
        p2 = warp_red_f(p2);
        if (lid == 0) {
            g_pc[blockIdx.x] = c2;
            g_pr[blockIdx.x] = r2;
            g_pp[blockIdx.x] = p2;
        }
    }

    // ---- last-block final reduction (no second launch) ----
    __shared__ int s_last;
    if (threadIdx.x == 0) {
        __threadfence();
        int prev = atomicAdd(&g_count, 1);
        s_last = (prev == gridDim.x - 1) ? 1 : 0;
    }
    __syncthreads();
    if (s_last) {
        double c = 0.0, r = 0.0, p = 0.0;
        for (int i = threadIdx.x; i < (int)gridDim.x; i += TPB) {
            c += (double)g_pc[i];
            r += (double)g_pr[i];
            p += (double)g_pp[i];
        }
        c = warp_red_d(c);
        r = warp_red_d(r);
        p = warp_red_d(p);
        __shared__ double sc[8], sr[8], sp[8];
        if (lid == 0) { sc[wid] = c; sr[wid] = r; sp[wid] = p; }
        __syncthreads();
        if (threadIdx.x == 0) {
            double tc = 0.0, tr = 0.0, tp = 0.0;
            #pragma unroll
            for (int i = 0; i < 8; ++i) { tc += sc[i]; tr += sr[i]; tp += sp[i]; }
            float pos_cnt = (float)tp;
            float norm = fmaxf(pos_cnt, 1.f);
            float cls_loss = (float)tc / norm;
            float reg_loss = (pos_cnt > 0.f) ? ((float)tr / (norm * 4.f)) : 0.f;
            out[0] = cls_loss + reg_loss;
            out[1] = cls_loss;
            out[2] = reg_loss;
            g_count = 0;   // reset for next graph replay
        }
    }
}

extern "C" void kernel_launch(void* const* d_in, const int* in_sizes, int n_in,
                              void* d_out, int out_size)
{
    const float*  cls = (const float*)d_in[0];
    const float4* box = (const float4*)d_in[1];
    const float4* anc = (const float4*)d_in[2];
    const float4* tb  = (const float4*)d_in[3];
    const int*    tl  = (const int*)d_in[4];
    float* out = (float*)d_out;

    int A = in_sizes[2] / 4;   // flattened anchor count (B*A)
    int T = in_sizes[4];       // flattened target count (B*T)
    if (T > MAXT) T = MAXT;

    int nblocks = (A + TPB * APT - 1) / (TPB * APT);   // 196608 -> 384
    if (nblocks > MAXBLOCKS) nblocks = MAXBLOCKS;

    retina_fused<<<nblocks, TPB>>>(cls, box, anc, tb, tl, out, A, T);
}

// round 5
// speedup vs baseline: 1.1231x; 1.0381x over previous
#include <cuda_runtime.h>
#include <math.h>

#define CLASSES 21
#define MAXT 256
#define TPB 256
#define MAXBLOCKS 4096

__device__ float g_pc[MAXBLOCKS];
__device__ float g_pr[MAXBLOCKS];
__device__ float g_pp[MAXBLOCKS];
__device__ int   g_count;   // zero-init; self-resets every launch (graph-replay safe)

__device__ __forceinline__ float warp_red_f(float v) {
    #pragma unroll
    for (int o = 16; o > 0; o >>= 1) v += __shfl_down_sync(0xffffffffu, v, o);
    return v;
}
__device__ __forceinline__ double warp_red_d(double v) {
    #pragma unroll
    for (int o = 16; o > 0; o >>= 1) v += __shfl_down_sync(0xffffffffu, v, o);
    return v;
}

__global__ void __launch_bounds__(TPB)
retina_fused(const float* __restrict__ cls,
             const float4* __restrict__ box,
             const float4* __restrict__ anc,
             const float4* __restrict__ tb,
             const int* __restrict__ tl,
             float* __restrict__ out,
             int A, int T)
{
    __shared__ float4 s_neg[MAXT];   // {tz, tw, -tx1, -ty1}
    __shared__ float4 s_org[MAXT];   // original xyxy (epilogue only)
    __shared__ float  s_ta[MAXT];
    __shared__ int    s_tl[MAXT];

    for (int t = threadIdx.x; t < T; t += TPB) {
        float4 b = tb[t];
        s_org[t] = b;
        s_neg[t] = make_float4(b.z, b.w, -b.x, -b.y);
        s_ta[t]  = (b.z - b.x) * (b.w - b.y);
        s_tl[t]  = tl[t];
    }
    __syncthreads();

    const int a = blockIdx.x * TPB + threadIdx.x;
    float cls_sum = 0.f, reg_sum = 0.f, posf = 0.f;

    if (a < A) {
        const float4 an = anc[a];
        const float az  = an.z,  aw = an.w;
        const float nax = -an.x, nay = -an.y;
        const float areaA = (an.z - an.x) * (an.w - an.y);

        // ---- approx IoU argmax: packed key (upper 24 bits of r, index in low 8) ----
        // signed IMNMX rejects r<0 automatically (sign bit survives the mask);
        // clamping only w kills the w<0 & h<0 false-positive case.
        int best = 255;                     // key(r=0, t=0)
        #pragma unroll 4
        for (int t = 0; t < T; ++t) {
            float4 q = s_neg[t];
            float ta = s_ta[t];
            float m1 = fminf(az,  q.x);
            float m2 = fminf(aw,  q.y);
            float n1 = fminf(nax, q.z);     // = -max(ax, tx1)
            float n2 = fminf(nay, q.w);     // = -max(ay, ty1)
            float w = m1 + n1;
            float h = m2 + n2;
            w = fmaxf(w, 0.f);
            float inter = w * h;
            float uni   = (areaA + ta) - inter;
            float r     = __fdividef(inter, uni);       // FMUL + MUFU.RCP
            int key = (__float_as_int(r) & 0xFFFFFF00) | (255 - t);  // LOP3
            best = max(best, key);                                   // IMNMX
        }
        const int tsel = 255 - (best & 0xFF);

        // ---- exact IoU for the winner (IEEE div, reference rounding) ----
        float4 tg = s_org[tsel];
        float w = fmaxf(fminf(an.z, tg.z) - fmaxf(an.x, tg.x), 0.f);
        float h = fmaxf(fminf(an.w, tg.w) - fmaxf(an.y, tg.y), 0.f);
        float inter = w * h;
        float uni   = areaA + s_ta[tsel] - inter;
        float iou   = __fdiv_rn(inter, fmaxf(uni, 1e-8f));
        const bool pos = (iou >= 0.5f);
        posf = pos ? 1.f : 0.f;
        const int lbl = pos ? s_tl[tsel] : 0;   // negatives: one_hot(0) => class 0 is "positive"

        // ---- focal loss: all classes as background, then correct class `lbl` ----
        const float* cp = cls + (size_t)a * CLASSES;
        float acc = 0.f;
        #pragma unroll
        for (int c = 0; c < CLASSES; ++c) {
            float x  = cp[c];
            float e  = __expf(-fabsf(x));
            float op = 1.f + e;
            float rc = __fdividef(1.f, op);
            float l1p = __logf(op);
            float sp  = l1p + fmaxf(x, 0.f);            // softplus(x)  (ce, t=0)
            float sg  = (x >= 0.f) ? rc : e * rc;       // sigmoid(x)   (1-pt, t=0)
            acc += sg * sg * sp;
        }
        cls_sum = 0.75f * acc;
        {   // correction for the single target class
            float x  = cp[lbl];
            float e  = __expf(-fabsf(x));
            float op = 1.f + e;
            float rc = __fdividef(1.f, op);
            float l1p = __logf(op);
            float sp_b = l1p + fmaxf(x, 0.f);           // softplus(x)
            float sg_p = (x >= 0.f) ? rc : e * rc;      // sigmoid(x)
            float sp_p = l1p + fmaxf(-x, 0.f);          // softplus(-x) (ce, t=1)
            float sg_n = (x >= 0.f) ? e * rc : rc;      // sigmoid(-x)  (1-pt, t=1)
            cls_sum += 0.25f * sg_n * sg_n * sp_p - 0.75f * sg_p * sg_p * sp_b;
        }

        // ---- regression (positives only) ----
        if (pos) {
            float4 bp = box[a];
            float awx = an.z - an.x, awy = an.w - an.y;
            float acx = (an.x + an.z) * 0.5f, acy = (an.y + an.w) * 0.5f;

            float ep0 = __fdiv_rn((bp.x + bp.z) * 0.5f - acx, awx);
            float ep1 = __fdiv_rn((bp.y + bp.w) * 0.5f - acy, awy);
            float ep2 = logf(__fdiv_rn(bp.z - bp.x, awx));
            float ep3 = logf(__fdiv_rn(bp.w - bp.y, awy));

            float et0 = __fdiv_rn((tg.x + tg.z) * 0.5f - acx, awx);
            float et1 = __fdiv_rn((tg.y + tg.w) * 0.5f - acy, awy);
            float et2 = logf(__fdiv_rn(tg.z - tg.x, awx));
            float et3 = logf(__fdiv_rn(tg.w - tg.y, awy));

            float d;
            d = fabsf(ep0 - et0); reg_sum += (d < 1.f) ? 0.5f * d * d : d - 0.5f;
            d = fabsf(ep1 - et1); reg_sum += (d < 1.f) ? 0.5f * d * d : d - 0.5f;
            d = fabsf(ep2 - et2); reg_sum += (d < 1.f) ? 0.5f * d * d : d - 0.5f;
            d = fabsf(ep3 - et3); reg_sum += (d < 1.f) ? 0.5f * d * d : d - 0.5f;
        }
    }

    // ---- deterministic block reduction ----
    __shared__ float red_c[8], red_r[8], red_p[8];
    float vc = warp_red_f(cls_sum);
    float vr = warp_red_f(reg_sum);
    float vp = warp_red_f(posf);
    int wid = threadIdx.x >> 5, lid = threadIdx.x & 31;
    if (lid == 0) { red_c[wid] = vc; red_r[wid] = vr; red_p[wid] = vp; }
    __syncthreads();
    if (wid == 0) {
        float c2 = (lid < 8) ? red_c[lid] : 0.f;
        float r2 = (lid < 8) ? red_r[lid] : 0.f;
        float p2 = (lid < 8) ? red_p[lid] : 0.f;
        c2 = warp_red_f(c2);
        r2 = warp_red_f(r2);
        p2 = warp_red_f(p2);
        if (lid == 0) {
            g_pc[blockIdx.x] = c2;
            g_pr[blockIdx.x] = r2;
            g_pp[blockIdx.x] = p2;
        }
    }

    // ---- last-block final reduction (single launch total) ----
    __shared__ int s_last;
    if (threadIdx.x == 0) {
        __threadfence();
        int prev = atomicAdd(&g_count, 1);
        s_last = (prev == gridDim.x - 1) ? 1 : 0;
    }
    __syncthreads();
    if (s_last) {
        double c = 0.0, r = 0.0, p = 0.0;
        for (int i = threadIdx.x; i < (int)gridDim.x; i += TPB) {
            c += (double)g_pc[i];
            r += (double)g_pr[i];
            p += (double)g_pp[i];
        }
        c = warp_red_d(c);
        r = warp_red_d(r);
        p = warp_red_d(p);
        __shared__ double sc[8], sr[8], sp[8];
        if (lid == 0) { sc[wid] = c; sr[wid] = r; sp[wid] = p; }
        __syncthreads();
        if (threadIdx.x == 0) {
            double tc = 0.0, tr = 0.0, tp = 0.0;
            #pragma unroll
            for (int i = 0; i < 8; ++i) { tc += sc[i]; tr += sr[i]; tp += sp[i]; }
            float pos_cnt = (float)tp;
            float norm = fmaxf(pos_cnt, 1.f);
            float cls_loss = (float)tc / norm;
            float reg_loss = (pos_cnt > 0.f) ? ((float)tr / (norm * 4.f)) : 0.f;
            out[0] = cls_loss + reg_loss;
            out[1] = cls_loss;
            out[2] = reg_loss;
            g_count = 0;
        }
    }
}

extern "C" void kernel_launch(void* const* d_in, const int* in_sizes, int n_in,
                              void* d_out, int out_size)
{
    const float*  cls = (const float*)d_in[0];
    const float4* box = (const float4*)d_in[1];
    const float4* anc = (const float4*)d_in[2];
    const float4* tb  = (const float4*)d_in[3];
    const int*    tl  = (const int*)d_in[4];
    float* out = (float*)d_out;

    int A = in_sizes[2] / 4;   // flattened anchors (B*A)
    int T = in_sizes[4];       // flattened targets (B*T)
    if (T > 255) T = 255;      // 8-bit index encoding capacity (T=200 here)

    int nblocks = (A + TPB - 1) / TPB;   // 196608 -> 768
    if (nblocks > MAXBLOCKS) nblocks = MAXBLOCKS;

    retina_fused<<<nblocks, TPB>>>(cls, box, anc, tb, tl, out, A, T);
}

// round 6
// speedup vs baseline: 1.2355x; 1.1001x over previous
#include <cuda_runtime.h>
#include <math.h>

#define CLASSES 21
#define MAXT 256
#define TPB 256
#define MAXBLOCKS 4096

__device__ float g_pc[MAXBLOCKS];
__device__ float g_pr[MAXBLOCKS];
__device__ float g_pp[MAXBLOCKS];
__device__ int   g_count;   // zero-init; self-resets every launch (graph-replay safe)

__device__ __forceinline__ float warp_red_f(float v) {
    #pragma unroll
    for (int o = 16; o > 0; o >>= 1) v += __shfl_down_sync(0xffffffffu, v, o);
    return v;
}
__device__ __forceinline__ double warp_red_d(double v) {
    #pragma unroll
    for (int o = 16; o > 0; o >>= 1) v += __shfl_down_sync(0xffffffffu, v, o);
    return v;
}

// CT > 0: compile-time trip count (full unroll, batched LDS). CT == 0: dynamic T.
template <int CT>
__global__ void __launch_bounds__(TPB, 8)
retina_fused(const float* __restrict__ cls,
             const float4* __restrict__ box,
             const float4* __restrict__ anc,
             const float4* __restrict__ tb,
             const int* __restrict__ tl,
             float* __restrict__ out,
             int A, int Tdyn)
{
    const int T = (CT > 0) ? CT : Tdyn;

    __shared__ float4 s_neg[MAXT];   // {tz, tw, -tx1, -ty1}
    __shared__ float4 s_org[MAXT];   // original xyxy (epilogue only)
    __shared__ float  s_ta[MAXT];
    __shared__ int    s_tl[MAXT];

    for (int t = threadIdx.x; t < T; t += TPB) {
        float4 b = tb[t];
        s_org[t] = b;
        s_neg[t] = make_float4(b.z, b.w, -b.x, -b.y);
        s_ta[t]  = (b.z - b.x) * (b.w - b.y);
        s_tl[t]  = tl[t];
    }
    __syncthreads();

    const int a = blockIdx.x * TPB + threadIdx.x;
    float cls_sum = 0.f, reg_sum = 0.f, posf = 0.f;

    if (a < A) {
        float cse, rse, pse;   // scoped results
        {
            const float4 an0 = anc[a];
            const float az  = an0.z,  aw = an0.w;
            const float nax = -an0.x, nay = -an0.y;
            const float areaA = (an0.z - an0.x) * (an0.w - an0.y);

            // ---- approx IoU argmax: packed key (upper 24 bits of r | (255-t)) ----
            // signed IMNMX rejects r<0 automatically; clamping w alone kills w<0&h<0.
            int best = 255;   // key(r=0, t=0)
            #pragma unroll
            for (int t = 0; t < T; ++t) {
                float4 q = s_neg[t];
                float ta = s_ta[t];
                float m1 = fminf(az,  q.x);
                float m2 = fminf(aw,  q.y);
                float n1 = fminf(nax, q.z);     // = -max(ax, tx1)
                float n2 = fminf(nay, q.w);     // = -max(ay, ty1)
                float w = m1 + n1;
                float h = m2 + n2;
                w = fmaxf(w, 0.f);
                float inter = w * h;
                float uni   = (areaA + ta) - inter;
                float r     = __fdividef(inter, uni);            // FMUL + MUFU.RCP
                int key = (__float_as_int(r) & 0xFFFFFF00) | (255 - t);
                best = max(best, key);                           // IMNMX
            }
            const int tsel = 255 - (best & 0xFF);

            // ---- exact IoU for the winner (IEEE div, reference rounding) ----
            float4 an = anc[a];            // reload (keeps hot-loop regs small)
            float4 tg = s_org[tsel];
            float areaAx = (an.z - an.x) * (an.w - an.y);
            float w = fmaxf(fminf(an.z, tg.z) - fmaxf(an.x, tg.x), 0.f);
            float h = fmaxf(fminf(an.w, tg.w) - fmaxf(an.y, tg.y), 0.f);
            float inter = w * h;
            float uni   = areaAx + s_ta[tsel] - inter;
            float iou   = __fdiv_rn(inter, fmaxf(uni, 1e-8f));
            const bool pos = (iou >= 0.5f);
            pse = pos ? 1.f : 0.f;
            const int lbl = pos ? s_tl[tsel] : 0;   // negatives: one_hot(0)

            // ---- focal loss: all classes as background, correct class `lbl` ----
            const float* cp = cls + (size_t)a * CLASSES;
            float acc = 0.f;
            #pragma unroll
            for (int c = 0; c < CLASSES; ++c) {
                float x  = cp[c];
                float e  = __expf(-fabsf(x));
                float op = 1.f + e;
                float rc = __fdividef(1.f, op);
                float l1p = __logf(op);
                float sp  = l1p + fmaxf(x, 0.f);          // softplus(x)  (ce, t=0)
                float sg  = (x >= 0.f) ? rc : e * rc;     // sigmoid(x)   (1-pt, t=0)
                acc += sg * sg * sp;
            }
            cse = 0.75f * acc;
            {   // single-class correction
                float x  = cp[lbl];
                float e  = __expf(-fabsf(x));
                float op = 1.f + e;
                float rc = __fdividef(1.f, op);
                float l1p = __logf(op);
                float sp_b = l1p + fmaxf(x, 0.f);
                float sg_p = (x >= 0.f) ? rc : e * rc;
                float sp_p = l1p + fmaxf(-x, 0.f);
                float sg_n = (x >= 0.f) ? e * rc : rc;
                cse += 0.25f * sg_n * sg_n * sp_p - 0.75f * sg_p * sg_p * sp_b;
            }

            // ---- regression (positives only) ----
            rse = 0.f;
            if (pos) {
                float4 bp = box[a];
                float awx = an.z - an.x, awy = an.w - an.y;
                float acx = (an.x + an.z) * 0.5f, acy = (an.y + an.w) * 0.5f;

                float ep0 = __fdiv_rn((bp.x + bp.z) * 0.5f - acx, awx);
                float ep1 = __fdiv_rn((bp.y + bp.w) * 0.5f - acy, awy);
                float ep2 = logf(__fdiv_rn(bp.z - bp.x, awx));
                float ep3 = logf(__fdiv_rn(bp.w - bp.y, awy));

                float et0 = __fdiv_rn((tg.x + tg.z) * 0.5f - acx, awx);
                float et1 = __fdiv_rn((tg.y + tg.w) * 0.5f - acy, awy);
                float et2 = logf(__fdiv_rn(tg.z - tg.x, awx));
                float et3 = logf(__fdiv_rn(tg.w - tg.y, awy));

                float d;
                d = fabsf(ep0 - et0); rse += (d < 1.f) ? 0.5f * d * d : d - 0.5f;
                d = fabsf(ep1 - et1); rse += (d < 1.f) ? 0.5f * d * d : d - 0.5f;
                d = fabsf(ep2 - et2); rse += (d < 1.f) ? 0.5f * d * d : d - 0.5f;
                d = fabsf(ep3 - et3); rse += (d < 1.f) ? 0.5f * d * d : d - 0.5f;
            }
        }
        cls_sum = cse; reg_sum = rse; posf = pse;
    }

    // ---- deterministic block reduction ----
    __shared__ float red_c[8], red_r[8], red_p[8];
    float vc = warp_red_f(cls_sum);
    float vr = warp_red_f(reg_sum);
    float vp = warp_red_f(posf);
    int wid = threadIdx.x >> 5, lid = threadIdx.x & 31;
    if (lid == 0) { red_c[wid] = vc; red_r[wid] = vr; red_p[wid] = vp; }
    __syncthreads();
    if (wid == 0) {
        float c2 = (lid < 8) ? red_c[lid] : 0.f;
        float r2 = (lid < 8) ? red_r[lid] : 0.f;
        float p2 = (lid < 8) ? red_p[lid] : 0.f;
        c2 = warp_red_f(c2);
        r2 = warp_red_f(r2);
        p2 = warp_red_f(p2);
        if (lid == 0) {
            g_pc[blockIdx.x] = c2;
            g_pr[blockIdx.x] = r2;
            g_pp[blockIdx.x] = p2;
        }
    }

    // ---- last-block final reduction (single launch total) ----
    __shared__ int s_last;
    if (threadIdx.x == 0) {
        __threadfence();
        int prev = atomicAdd(&g_count, 1);
        s_last = (prev == gridDim.x - 1) ? 1 : 0;
    }
    __syncthreads();
    if (s_last) {
        double c = 0.0, r = 0.0, p = 0.0;
        for (int i = threadIdx.x; i < (int)gridDim.x; i += TPB) {
            c += (double)g_pc[i];
            r += (double)g_pr[i];
            p += (double)g_pp[i];
        }
        c = warp_red_d(c);
        r = warp_red_d(r);
        p = warp_red_d(p);
        __shared__ double sc[8], sr[8], sp[8];
        if (lid == 0) { sc[wid] = c; sr[wid] = r; sp[wid] = p; }
        __syncthreads();
        if (threadIdx.x == 0) {
            double tc = 0.0, tr = 0.0, tp = 0.0;
            #pragma unroll
            for (int i = 0; i < 8; ++i) { tc += sc[i]; tr += sr[i]; tp += sp[i]; }
            float pos_cnt = (float)tp;
            float norm = fmaxf(pos_cnt, 1.f);
            float cls_loss = (float)tc / norm;
            float reg_loss = (pos_cnt > 0.f) ? ((float)tr / (norm * 4.f)) : 0.f;
            out[0] = cls_loss + reg_loss;
            out[1] = cls_loss;
            out[2] = reg_loss;
            g_count = 0;
        }
    }
}

extern "C" void kernel_launch(void* const* d_in, const int* in_sizes, int n_in,
                              void* d_out, int out_size)
{
    const float*  cls = (const float*)d_in[0];
    const float4* box = (const float4*)d_in[1];
    const float4* anc = (const float4*)d_in[2];
    const float4* tb  = (const float4*)d_in[3];
    const int*    tl  = (const int*)d_in[4];
    float* out = (float*)d_out;

    int A = in_sizes[2] / 4;   // flattened anchors (B*A)
    int T = in_sizes[4];       // flattened targets (B*T)
    if (T > 255) T = 255;      // 8-bit index encoding capacity

    int nblocks = (A + TPB - 1) / TPB;   // 196608 -> 768
    if (nblocks > MAXBLOCKS) nblocks = MAXBLOCKS;

    if (T == 200) {
        retina_fused<200><<<nblocks, TPB>>>(cls, box, anc, tb, tl, out, A, T);
    } else {
        retina_fused<0><<<nblocks, TPB>>>(cls, box, anc, tb, tl, out, A, T);
    }
}

// round 7
// speedup vs baseline: 1.2955x; 1.0486x over previous
#include <cuda_runtime.h>
#include <math.h>

#define CLASSES 21
#define MAXT 256
#define TPB 256
#define MAXBLOCKS 4096
#define MAXA 262144

__device__ int   g_key[MAXA];     // zero-init; packed argmax keys; reset by phase2
__device__ float g_pc[MAXBLOCKS];
__device__ float g_pr[MAXBLOCKS];
__device__ float g_pp[MAXBLOCKS];
__device__ int   g_count;         // zero-init; reset by phase2

__device__ __forceinline__ float warp_red_f(float v) {
    #pragma unroll
    for (int o = 16; o > 0; o >>= 1) v += __shfl_down_sync(0xffffffffu, v, o);
    return v;
}
__device__ __forceinline__ double warp_red_d(double v) {
    #pragma unroll
    for (int o = 16; o > 0; o >>= 1) v += __shfl_down_sync(0xffffffffu, v, o);
    return v;
}

// ---------------- Phase 1: IoU argmax over a T-slice, merged via atomicMax ----------------
// Rank by r' = inter / (areaA + ta)  (monotone transform of IoU; exact threshold redone in p2).
// Key: upper 24 bits of r' | (255 - t). Negative r' -> negative key -> loses signed max.
template <int CTT>
__global__ void __launch_bounds__(TPB, 8)
retina_p1(const float4* __restrict__ anc,
          const float4* __restrict__ tb,
          int A, int Tdyn)
{
    const int t0  = blockIdx.y * (CTT > 0 ? CTT : Tdyn);
    const int cnt = (CTT > 0) ? CTT : min(Tdyn, Tdyn /*dummy*/);
    // dynamic fallback: each y-block covers [t0, min(t0+Tdyn_slice,...)) handled below

    __shared__ float4 s_neg[CTT > 0 ? CTT : MAXT];   // {tz, tw, -tx1, -ty1}
    __shared__ float  s_ta [CTT > 0 ? CTT : MAXT];

    int ccount;
    if (CTT > 0) {
        ccount = CTT;
    } else {
        ccount = Tdyn - t0;           // generic path: gridDim.y slices of size Tdyn? (host passes slice via Tdyn)
        if (ccount > MAXT) ccount = MAXT;
    }
    (void)cnt;

    for (int t = threadIdx.x; t < ccount; t += TPB) {
        float4 b = tb[t0 + t];
        s_neg[t] = make_float4(b.z, b.w, -b.x, -b.y);
        s_ta[t]  = (b.z - b.x) * (b.w - b.y);
    }
    __syncthreads();

    const int a = blockIdx.x * TPB + threadIdx.x;
    if (a >= A) return;

    const float4 an = anc[a];
    const float az  = an.z,  aw = an.w;
    const float nax = -an.x, nay = -an.y;
    const float areaA = (an.z - an.x) * (an.w - an.y);
    const int idxbase = 255 - t0;

    int best = 0;
    #pragma unroll
    for (int tt = 0; tt < (CTT > 0 ? CTT : MAXT); ++tt) {
        if (CTT == 0 && tt >= ccount) break;
        float4 q = s_neg[tt];
        float ta = s_ta[tt];
        float m1 = fminf(az,  q.x);
        float m2 = fminf(aw,  q.y);
        float n1 = fminf(nax, q.z);          // = -max(ax, tx1)
        float n2 = fminf(nay, q.w);          // = -max(ay, ty1)
        float w  = fmaxf(m1 + n1, 0.f);
        float h  = m2 + n2;
        float inter = w * h;                 // <=0 never wins (key goes negative/zero)
        float S  = areaA + ta;               // MUFU.RCP path independent of min/max chain
        float r  = __fdividef(inter, S);     // rank-equivalent to IoU
        int key = (__float_as_int(r) & 0xFFFFFF00) | (idxbase - tt);
        best = max(best, key);
    }
    atomicMax(&g_key[a], best);              // REDG.MAX, deterministic merge
}

// ---------------- Phase 2: decode winner, exact IoU, focal + regression + reduce ----------------
__global__ void __launch_bounds__(TPB)
retina_p2(const float* __restrict__ cls,
          const float4* __restrict__ box,
          const float4* __restrict__ anc,
          const float4* __restrict__ tb,
          const int* __restrict__ tl,
          float* __restrict__ out,
          int A, int T)
{
    __shared__ float4 s_org[MAXT];
    __shared__ float  s_ta[MAXT];
    __shared__ int    s_tl[MAXT];

    for (int t = threadIdx.x; t < T; t += TPB) {
        float4 b = tb[t];
        s_org[t] = b;
        s_ta[t]  = (b.z - b.x) * (b.w - b.y);
        s_tl[t]  = tl[t];
    }
    __syncthreads();

    const int a = blockIdx.x * TPB + threadIdx.x;
    float cls_sum = 0.f, reg_sum = 0.f, posf = 0.f;

    if (a < A) {
        int key = g_key[a];
        g_key[a] = 0;                         // reset for next graph replay
        int tsel = 255 - (key & 0xFF);
        if (tsel >= T) tsel = 0;              // all-zero-IoU corner: argmax==0, pos=false below

        float4 an = anc[a];
        float4 tg = s_org[tsel];
        float areaA = (an.z - an.x) * (an.w - an.y);
        float w = fmaxf(fminf(an.z, tg.z) - fmaxf(an.x, tg.x), 0.f);
        float h = fmaxf(fminf(an.w, tg.w) - fmaxf(an.y, tg.y), 0.f);
        float inter = w * h;
        float uni   = areaA + s_ta[tsel] - inter;
        float iou   = __fdiv_rn(inter, fmaxf(uni, 1e-8f));
        const bool pos = (iou >= 0.5f);
        posf = pos ? 1.f : 0.f;
        const int lbl = pos ? s_tl[tsel] : 0;     // negatives: one_hot(0)

        // focal: all classes as background, then correct class `lbl`
        const float* cp = cls + (size_t)a * CLASSES;
        float acc = 0.f;
        #pragma unroll
        for (int c = 0; c < CLASSES; ++c) {
            float x  = cp[c];
            float e  = __expf(-fabsf(x));
            float op = 1.f + e;
            float rc = __fdividef(1.f, op);
            float l1p = __logf(op);
            float sp  = l1p + fmaxf(x, 0.f);           // softplus(x)  (ce, t=0)
            float sg  = (x >= 0.f) ? rc : e * rc;      // sigmoid(x)   (1-pt, t=0)
            acc += sg * sg * sp;
        }
        cls_sum = 0.75f * acc;
        {
            float x  = cp[lbl];
            float e  = __expf(-fabsf(x));
            float op = 1.f + e;
            float rc = __fdividef(1.f, op);
            float l1p = __logf(op);
            float sp_b = l1p + fmaxf(x, 0.f);
            float sg_p = (x >= 0.f) ? rc : e * rc;
            float sp_p = l1p + fmaxf(-x, 0.f);
            float sg_n = (x >= 0.f) ? e * rc : rc;
            cls_sum += 0.25f * sg_n * sg_n * sp_p - 0.75f * sg_p * sg_p * sp_b;
        }

        if (pos) {
            float4 bp = box[a];
            float awx = an.z - an.x, awy = an.w - an.y;
            float acx = (an.x + an.z) * 0.5f, acy = (an.y + an.w) * 0.5f;

            float ep0 = __fdiv_rn((bp.x + bp.z) * 0.5f - acx, awx);
            float ep1 = __fdiv_rn((bp.y + bp.w) * 0.5f - acy, awy);
            float ep2 = logf(__fdiv_rn(bp.z - bp.x, awx));
            float ep3 = logf(__fdiv_rn(bp.w - bp.y, awy));

            float et0 = __fdiv_rn((tg.x + tg.z) * 0.5f - acx, awx);
            float et1 = __fdiv_rn((tg.y + tg.w) * 0.5f - acy, awy);
            float et2 = logf(__fdiv_rn(tg.z - tg.x, awx));
            float et3 = logf(__fdiv_rn(tg.w - tg.y, awy));

            float d;
            d = fabsf(ep0 - et0); reg_sum += (d < 1.f) ? 0.5f * d * d : d - 0.5f;
            d = fabsf(ep1 - et1); reg_sum += (d < 1.f) ? 0.5f * d * d : d - 0.5f;
            d = fabsf(ep2 - et2); reg_sum += (d < 1.f) ? 0.5f * d * d : d - 0.5f;
            d = fabsf(ep3 - et3); reg_sum += (d < 1.f) ? 0.5f * d * d : d - 0.5f;
        }
    }

    // deterministic block reduction
    __shared__ float red_c[8], red_r[8], red_p[8];
    float vc = warp_red_f(cls_sum);
    float vr = warp_red_f(reg_sum);
    float vp = warp_red_f(posf);
    int wid = threadIdx.x >> 5, lid = threadIdx.x & 31;
    if (lid == 0) { red_c[wid] = vc; red_r[wid] = vr; red_p[wid] = vp; }
    __syncthreads();
    if (wid == 0) {
        float c2 = (lid < 8) ? red_c[lid] : 0.f;
        float r2 = (lid < 8) ? red_r[lid] : 0.f;
        float p2 = (lid < 8) ? red_p[lid] : 0.f;
        c2 = warp_red_f(c2);
        r2 = warp_red_f(r2);
        p2 = warp_red_f(p2);
        if (lid == 0) {
            g_pc[blockIdx.x] = c2;
            g_pr[blockIdx.x] = r2;
            g_pp[blockIdx.x] = p2;
        }
    }

    // last-block final reduction
    __shared__ int s_last;
    if (threadIdx.x == 0) {
        __threadfence();
        int prev = atomicAdd(&g_count, 1);
        s_last = (prev == (int)gridDim.x - 1) ? 1 : 0;
    }
    __syncthreads();
    if (s_last) {
        double c = 0.0, r = 0.0, p = 0.0;
        for (int i = threadIdx.x; i < (int)gridDim.x; i += TPB) {
            c += (double)g_pc[i];
            r += (double)g_pr[i];
            p += (double)g_pp[i];
        }
        c = warp_red_d(c);
        r = warp_red_d(r);
        p = warp_red_d(p);
        __shared__ double sc[8], sr[8], sp[8];
        if (lid == 0) { sc[wid] = c; sr[wid] = r; sp[wid] = p; }
        __syncthreads();
        if (threadIdx.x == 0) {
            double tc = 0.0, tr = 0.0, tp = 0.0;
            #pragma unroll
            for (int i = 0; i < 8; ++i) { tc += sc[i]; tr += sr[i]; tp += sp[i]; }
            float pos_cnt = (float)tp;
            float norm = fmaxf(pos_cnt, 1.f);
            float cls_loss = (float)tc / norm;
            float reg_loss = (pos_cnt > 0.f) ? ((float)tr / (norm * 4.f)) : 0.f;
            out[0] = cls_loss + reg_loss;
            out[1] = cls_loss;
            out[2] = reg_loss;
            g_count = 0;
        }
    }
}

extern "C" void kernel_launch(void* const* d_in, const int* in_sizes, int n_in,
                              void* d_out, int out_size)
{
    const float*  cls = (const float*)d_in[0];
    const float4* box = (const float4*)d_in[1];
    const float4* anc = (const float4*)d_in[2];
    const float4* tb  = (const float4*)d_in[3];
    const int*    tl  = (const int*)d_in[4];
    float* out = (float*)d_out;

    int A = in_sizes[2] / 4;   // flattened anchors (B*A)
    int T = in_sizes[4];       // flattened targets (B*T)
    if (T > 255) T = 255;      // 8-bit index encoding capacity
    if (A > MAXA) A = MAXA;

    int gx = (A + TPB - 1) / TPB;          // 768
    if (gx > MAXBLOCKS) gx = MAXBLOCKS;

    if (T == 200) {
        dim3 g1(gx, 4);                    // 4 slices x 50 targets -> 3072 blocks
        retina_p1<50><<<g1, TPB>>>(anc, tb, A, T);
    } else {
        dim3 g1(gx, 1);                    // generic: single slice of all T
        retina_p1<0><<<g1, TPB>>>(anc, tb, A, T);
    }
    retina_p2<<<gx, TPB>>>(cls, box, anc, tb, tl, out, A, T);
}